// round 2
// baseline (speedup 1.0000x reference)
#include <cuda_runtime.h>
#include <cstddef>

// LSTM autoencoder, fused single kernel.
// B=256, T=4096, IN_DIM=1, HID=32, Z=16.
// One warp per batch element; lane j owns encoder hidden unit j.

#define FULL_MASK 0xFFFFFFFFu

namespace {
constexpr int Bb  = 256;
constexpr int Tt  = 4096;
constexpr int HID = 32;
constexpr int Zz  = 16;

__device__ __forceinline__ float sigf(float x) {
    // 1/(1+e^-x); expf overflow at very negative x gives inf -> 0, correct.
    return __fdividef(1.0f, 1.0f + __expf(-x));
}

__device__ __forceinline__ float tanh_fast(float x) {
    // sign-safe: exp of non-positive argument only, no overflow.
    float ax = fabsf(x);
    float e  = __expf(-2.0f * ax);
    float t  = __fdividef(1.0f - e, 1.0f + e);
    return copysignf(t, x);
}
} // namespace

__global__ __launch_bounds__(128, 1)
void lstm_ae_kernel(const float* __restrict__ x,
                    const float* __restrict__ enc_Wih,
                    const float* __restrict__ enc_Whh,
                    const float* __restrict__ enc_bih,
                    const float* __restrict__ enc_bhh,
                    const float* __restrict__ toz_W,
                    const float* __restrict__ toz_b,
                    const float* __restrict__ fromz_W,
                    const float* __restrict__ fromz_b,
                    const float* __restrict__ dec_Wih,
                    const float* __restrict__ dec_Whh,
                    const float* __restrict__ dec_bih,
                    const float* __restrict__ dec_bhh,
                    float* __restrict__ out)
{
    const int lane = threadIdx.x & 31;
    const int warp = threadIdx.x >> 5;
    const int b    = blockIdx.x * 4 + warp;   // 64 blocks x 4 warps = 256
    const int j    = lane;                    // hidden unit owned by this lane

    // ---- encoder weights for unit j (rows j, j+32, j+64, j+96 of Whh) ----
    float w0[HID], w1[HID], w2[HID], w3[HID];
#pragma unroll
    for (int k4 = 0; k4 < HID / 4; ++k4) {
        float4 v0 = *reinterpret_cast<const float4*>(enc_Whh + (j      ) * HID + k4 * 4);
        float4 v1 = *reinterpret_cast<const float4*>(enc_Whh + (j + 32 ) * HID + k4 * 4);
        float4 v2 = *reinterpret_cast<const float4*>(enc_Whh + (j + 64 ) * HID + k4 * 4);
        float4 v3 = *reinterpret_cast<const float4*>(enc_Whh + (j + 96 ) * HID + k4 * 4);
        w0[k4*4+0]=v0.x; w0[k4*4+1]=v0.y; w0[k4*4+2]=v0.z; w0[k4*4+3]=v0.w;
        w1[k4*4+0]=v1.x; w1[k4*4+1]=v1.y; w1[k4*4+2]=v1.z; w1[k4*4+3]=v1.w;
        w2[k4*4+0]=v2.x; w2[k4*4+1]=v2.y; w2[k4*4+2]=v2.z; w2[k4*4+3]=v2.w;
        w3[k4*4+0]=v3.x; w3[k4*4+1]=v3.y; w3[k4*4+2]=v3.z; w3[k4*4+3]=v3.w;
    }
    const float a0 = enc_bih[j     ] + enc_bhh[j     ];
    const float a1 = enc_bih[j + 32] + enc_bhh[j + 32];
    const float a2 = enc_bih[j + 64] + enc_bhh[j + 64];
    const float a3 = enc_bih[j + 96] + enc_bhh[j + 96];
    const float wx0 = enc_Wih[j     ];   // IN_DIM = 1
    const float wx1 = enc_Wih[j + 32];
    const float wx2 = enc_Wih[j + 64];
    const float wx3 = enc_Wih[j + 96];

    // ---- encoder recurrence ----
    float h = 0.0f, c = 0.0f;
    const float* xb = x + (size_t)b * Tt;

    for (int t0 = 0; t0 < Tt; t0 += 32) {
        float xv = xb[t0 + lane];          // coalesced prefetch of 32 inputs
#pragma unroll 1
        for (int s = 0; s < 32; ++s) {
            float xs = __shfl_sync(FULL_MASK, xv, s);
            float gi = fmaf(xs, wx0, a0);
            float gf = fmaf(xs, wx1, a1);
            float gg = fmaf(xs, wx2, a2);
            float go = fmaf(xs, wx3, a3);
#pragma unroll
            for (int k = 0; k < HID; ++k) {
                float hk = __shfl_sync(FULL_MASK, h, k);
                gi = fmaf(w0[k], hk, gi);
                gf = fmaf(w1[k], hk, gf);
                gg = fmaf(w2[k], hk, gg);
                go = fmaf(w3[k], hk, go);
            }
            float ig = sigf(gi);
            float fg = sigf(gf);
            float gu = tanh_fast(gg);
            float og = sigf(go);
            c = fmaf(fg, c, ig * gu);
            h = og * tanh_fast(c);
        }
    }

    // ---- bottleneck projections (once per batch) ----
    float hv[HID];
#pragma unroll
    for (int k = 0; k < HID; ++k) hv[k] = __shfl_sync(FULL_MASK, h, k);

    float zv[Zz];
#pragma unroll
    for (int m = 0; m < Zz; ++m) {
        float acc = toz_b[m];
#pragma unroll
        for (int k = 0; k < HID; ++k) acc = fmaf(toz_W[m * HID + k], hv[k], acc);
        zv[m] = acc;
    }
    float acc0 = fromz_b[j];
#pragma unroll
    for (int m = 0; m < Zz; ++m) acc0 = fmaf(fromz_W[j * Zz + m], zv[m], acc0);
    float h0 = tanh_fast(acc0);

    float h0v[HID];
#pragma unroll
    for (int k = 0; k < HID; ++k) h0v[k] = __shfl_sync(FULL_MASK, h0, k);

    // ---- decoder: hidden dim 1, input constant over time ----
    float xg[4], wh[4];
#pragma unroll
    for (int g = 0; g < 4; ++g) {
        float a = dec_bih[g] + dec_bhh[g];
#pragma unroll
        for (int k = 0; k < HID; ++k) a = fmaf(dec_Wih[g * HID + k], h0v[k], a);
        xg[g] = a;
        wh[g] = dec_Whh[g];   // [4,1]
    }

    float dh = 0.0f, dc = 0.0f, keep = 0.0f;
    float* ob = out + (size_t)b * Tt;

    for (int t0 = 0; t0 < Tt; t0 += 32) {
#pragma unroll 1
        for (int s = 0; s < 32; ++s) {
            float gi = fmaf(wh[0], dh, xg[0]);
            float gf = fmaf(wh[1], dh, xg[1]);
            float gg = fmaf(wh[2], dh, xg[2]);
            float go = fmaf(wh[3], dh, xg[3]);
            float ig = sigf(gi);
            float fg = sigf(gf);
            float gu = tanh_fast(gg);
            float og = sigf(go);
            dc = fmaf(fg, dc, ig * gu);
            dh = og * tanh_fast(dc);
            if (lane == s) keep = dh;   // lane s archives step t0+s
        }
        ob[t0 + lane] = keep;           // coalesced 128B store per warp
    }
}

extern "C" void kernel_launch(void* const* d_in, const int* in_sizes, int n_in,
                              void* d_out, int out_size)
{
    (void)in_sizes; (void)n_in; (void)out_size;
    const float* x        = (const float*)d_in[0];
    const float* enc_Wih  = (const float*)d_in[1];
    const float* enc_Whh  = (const float*)d_in[2];
    const float* enc_bih  = (const float*)d_in[3];
    const float* enc_bhh  = (const float*)d_in[4];
    const float* toz_W    = (const float*)d_in[5];
    const float* toz_b    = (const float*)d_in[6];
    const float* fromz_W  = (const float*)d_in[7];
    const float* fromz_b  = (const float*)d_in[8];
    const float* dec_Wih  = (const float*)d_in[9];
    const float* dec_Whh  = (const float*)d_in[10];
    const float* dec_bih  = (const float*)d_in[11];
    const float* dec_bhh  = (const float*)d_in[12];
    float* out = (float*)d_out;

    lstm_ae_kernel<<<64, 128>>>(x, enc_Wih, enc_Whh, enc_bih, enc_bhh,
                                toz_W, toz_b, fromz_W, fromz_b,
                                dec_Wih, dec_Whh, dec_bih, dec_bhh, out);
}

// round 3
// speedup vs baseline: 1.6369x; 1.6369x over previous
#include <cuda_runtime.h>
#include <cstddef>

// LSTM autoencoder, fused single kernel. B=256, T=4096, IN_DIM=1, HID=32, Z=16.
// One warp per batch element, one warp per SMSP (64 blocks x 128 threads).
// Encoder matvec uses Blackwell packed fma.rn.f32x2 with (even,odd) pair
// accumulation; h exchanged via double-buffered shared memory (1 STS + 8 LDS.128
// per step instead of 32 SHFL). Decoder uses exact fixed-point early exit.

#define FULL_MASK 0xFFFFFFFFu

namespace {
constexpr int Tt  = 4096;
constexpr int HID = 32;
constexpr int Zz  = 16;

__device__ __forceinline__ float sigf(float x) {
    return __fdividef(1.0f, 1.0f + __expf(-x));
}
__device__ __forceinline__ float tanh_fast(float x) {
    float ax = fabsf(x);
    float e  = __expf(-2.0f * ax);
    float t  = __fdividef(1.0f - e, 1.0f + e);
    return copysignf(t, x);
}

__device__ __forceinline__ unsigned long long pack2(float lo, float hi) {
    unsigned long long r;
    asm("mov.b64 %0, {%1, %2};" : "=l"(r) : "f"(lo), "f"(hi));
    return r;
}
__device__ __forceinline__ float2 unpack2(unsigned long long v) {
    float2 f;
    asm("mov.b64 {%0, %1}, %2;" : "=f"(f.x), "=f"(f.y) : "l"(v));
    return f;
}
__device__ __forceinline__ void ffma2(unsigned long long& acc,
                                      unsigned long long a,
                                      unsigned long long b) {
    asm("fma.rn.f32x2 %0, %1, %2, %0;" : "+l"(acc) : "l"(a), "l"(b));
}
} // namespace

__global__ __launch_bounds__(128, 1)
void lstm_ae_kernel(const float* __restrict__ x,
                    const float* __restrict__ enc_Wih,
                    const float* __restrict__ enc_Whh,
                    const float* __restrict__ enc_bih,
                    const float* __restrict__ enc_bhh,
                    const float* __restrict__ toz_W,
                    const float* __restrict__ toz_b,
                    const float* __restrict__ fromz_W,
                    const float* __restrict__ fromz_b,
                    const float* __restrict__ dec_Wih,
                    const float* __restrict__ dec_Whh,
                    const float* __restrict__ dec_bih,
                    const float* __restrict__ dec_bhh,
                    float* __restrict__ out)
{
    __shared__ __align__(16) float hbuf[4][2][HID];

    const int lane = threadIdx.x & 31;
    const int warp = threadIdx.x >> 5;
    const int b    = blockIdx.x * 4 + warp;   // 64 blocks x 4 warps = 256
    const int j    = lane;

    // ---- packed encoder recurrent weights: (even,odd) k pairs per gate ----
    unsigned long long wp0[HID/2], wp1[HID/2], wp2[HID/2], wp3[HID/2];
#pragma unroll
    for (int m = 0; m < HID / 2; ++m) {
        wp0[m] = pack2(enc_Whh[(j      ) * HID + 2*m], enc_Whh[(j      ) * HID + 2*m + 1]);
        wp1[m] = pack2(enc_Whh[(j + 32 ) * HID + 2*m], enc_Whh[(j + 32 ) * HID + 2*m + 1]);
        wp2[m] = pack2(enc_Whh[(j + 64 ) * HID + 2*m], enc_Whh[(j + 64 ) * HID + 2*m + 1]);
        wp3[m] = pack2(enc_Whh[(j + 96 ) * HID + 2*m], enc_Whh[(j + 96 ) * HID + 2*m + 1]);
    }
    const float a0 = enc_bih[j     ] + enc_bhh[j     ];
    const float a1 = enc_bih[j + 32] + enc_bhh[j + 32];
    const float a2 = enc_bih[j + 64] + enc_bhh[j + 64];
    const float a3 = enc_bih[j + 96] + enc_bhh[j + 96];
    const float wx0 = enc_Wih[j     ];
    const float wx1 = enc_Wih[j + 32];
    const float wx2 = enc_Wih[j + 64];
    const float wx3 = enc_Wih[j + 96];

    // ---- encoder recurrence ----
    float h = 0.0f, c = 0.0f;
    const float* xb = x + (size_t)b * Tt;

    for (int t0 = 0; t0 < Tt; t0 += 32) {
        float xv = xb[t0 + lane];                 // coalesced input prefetch
#pragma unroll 2
        for (int s = 0; s < 32; ++s) {
            hbuf[warp][s & 1][lane] = h;          // publish own h
            float xs = __shfl_sync(FULL_MASK, xv, s);
            // x-term + bias, folded into accumulator lo-half
            unsigned long long acc0 = pack2(fmaf(xs, wx0, a0), 0.0f);
            unsigned long long acc1 = pack2(fmaf(xs, wx1, a1), 0.0f);
            unsigned long long acc2 = pack2(fmaf(xs, wx2, a2), 0.0f);
            unsigned long long acc3 = pack2(fmaf(xs, wx3, a3), 0.0f);
            __syncwarp();
            const ulonglong2* hp =
                reinterpret_cast<const ulonglong2*>(hbuf[warp][s & 1]);
#pragma unroll
            for (int i = 0; i < HID / 4; ++i) {   // 8 x LDS.128 -> 16 pairs
                ulonglong2 q = hp[i];
                ffma2(acc0, wp0[2*i    ], q.x);
                ffma2(acc1, wp1[2*i    ], q.x);
                ffma2(acc2, wp2[2*i    ], q.x);
                ffma2(acc3, wp3[2*i    ], q.x);
                ffma2(acc0, wp0[2*i + 1], q.y);
                ffma2(acc1, wp1[2*i + 1], q.y);
                ffma2(acc2, wp2[2*i + 1], q.y);
                ffma2(acc3, wp3[2*i + 1], q.y);
            }
            float2 u0 = unpack2(acc0);
            float2 u1 = unpack2(acc1);
            float2 u2 = unpack2(acc2);
            float2 u3 = unpack2(acc3);
            float ig = sigf(u0.x + u0.y);
            float fg = sigf(u1.x + u1.y);
            float gu = tanh_fast(u2.x + u2.y);
            float og = sigf(u3.x + u3.y);
            c = fmaf(fg, c, ig * gu);
            h = og * tanh_fast(c);
        }
    }

    // ---- bottleneck projections ----
    float hv[HID];
#pragma unroll
    for (int k = 0; k < HID; ++k) hv[k] = __shfl_sync(FULL_MASK, h, k);

    float zv[Zz];
#pragma unroll
    for (int m = 0; m < Zz; ++m) {
        float acc = toz_b[m];
#pragma unroll
        for (int k = 0; k < HID; ++k) acc = fmaf(toz_W[m * HID + k], hv[k], acc);
        zv[m] = acc;
    }
    float acc0f = fromz_b[j];
#pragma unroll
    for (int m = 0; m < Zz; ++m) acc0f = fmaf(fromz_W[j * Zz + m], zv[m], acc0f);
    float h0 = tanh_fast(acc0f);

    float h0v[HID];
#pragma unroll
    for (int k = 0; k < HID; ++k) h0v[k] = __shfl_sync(FULL_MASK, h0, k);

    // ---- decoder: hidden dim 1, constant input over time ----
    float xg[4], wh[4];
#pragma unroll
    for (int g = 0; g < 4; ++g) {
        float a = dec_bih[g] + dec_bhh[g];
#pragma unroll
        for (int k = 0; k < HID; ++k) a = fmaf(dec_Wih[g * HID + k], h0v[k], a);
        xg[g] = a;
        wh[g] = dec_Whh[g];
    }

    float dh = 0.0f, dc = 0.0f, keep = 0.0f;
    float* ob = out + (size_t)b * Tt;

    int t0 = 0;
    for (; t0 < Tt; t0 += 32) {
        float sh = dh, sc = dc;                   // state at block start
#pragma unroll 1
        for (int s = 0; s < 32; ++s) {
            float gi = fmaf(wh[0], dh, xg[0]);
            float gf = fmaf(wh[1], dh, xg[1]);
            float gg = fmaf(wh[2], dh, xg[2]);
            float go = fmaf(wh[3], dh, xg[3]);
            float ig = sigf(gi);
            float fg = sigf(gf);
            float gu = tanh_fast(gg);
            float og = sigf(go);
            dc = fmaf(fg, dc, ig * gu);
            dh = og * tanh_fast(dc);
            if (lane == s) keep = dh;             // lane s archives step t0+s
        }
        ob[t0 + lane] = keep;                     // coalesced 128B store
        if (dh == sh && dc == sc) {               // exact fixed point / period
            t0 += 32;                             // deterministic map => all
            break;                                // later blocks repeat `keep`
        }
    }
    for (; t0 < Tt; t0 += 32) ob[t0 + lane] = keep;
}

extern "C" void kernel_launch(void* const* d_in, const int* in_sizes, int n_in,
                              void* d_out, int out_size)
{
    (void)in_sizes; (void)n_in; (void)out_size;
    const float* x        = (const float*)d_in[0];
    const float* enc_Wih  = (const float*)d_in[1];
    const float* enc_Whh  = (const float*)d_in[2];
    const float* enc_bih  = (const float*)d_in[3];
    const float* enc_bhh  = (const float*)d_in[4];
    const float* toz_W    = (const float*)d_in[5];
    const float* toz_b    = (const float*)d_in[6];
    const float* fromz_W  = (const float*)d_in[7];
    const float* fromz_b  = (const float*)d_in[8];
    const float* dec_Wih  = (const float*)d_in[9];
    const float* dec_Whh  = (const float*)d_in[10];
    const float* dec_bih  = (const float*)d_in[11];
    const float* dec_bhh  = (const float*)d_in[12];
    float* out = (float*)d_out;

    lstm_ae_kernel<<<64, 128>>>(x, enc_Wih, enc_Whh, enc_bih, enc_bhh,
                                toz_W, toz_b, fromz_W, fromz_b,
                                dec_Wih, dec_Whh, dec_bih, dec_bhh, out);
}